// round 2
// baseline (speedup 1.0000x reference)
#include <cuda_runtime.h>

// ---------------------------------------------------------------------------
// MeshUpConv: 3x SplineConv (kernel 3x3, degree 2, open spline) on GB300.
//
// Restructure: msg_e = sum_k B[e,k] * (x[src_e] @ W[k])
//   -> per layer: dense GEMM  Y[n, k*32+c] = sum_i x[n,i] * W[k,i,c]
//                 plus self term agg[n,c] = x[n] @ root + bias
//   -> edge pass: warp per edge, lane = channel:
//                 acc_c = sum_k B[e,k] * Y[src, k*32+c];  RED.add agg[dst,c]
//
// relu + concat(skip) fused into the next layer's GEMM input load.
// NOTE: harness converts int64 inputs to int32 -> edge_index is const int*.
// ---------------------------------------------------------------------------

#define NMAX 50000
#define CKOUT 288          // K * C_OUT = 9 * 32

__device__ float g_Y[(size_t)NMAX * CKOUT];     // per-layer Y scratch (reused)
__device__ float g_agg1[(size_t)NMAX * 32];     // layer-1 output (pre-relu)
__device__ float g_agg2[(size_t)NMAX * 32];     // layer-2 output (pre-relu)

// ---------------------------------------------------------------------------
// GEMM kernel: 320 threads = 320 output columns (288 Y cols + 32 self cols).
// Each thread keeps its W column (CIN floats) in registers; an 8-node x tile
// is staged in shared and broadcast-read (LDS.128) -> FMA-bound inner loop.
//   CIN : total input channels (64 or 32)
//   CA  : channels taken from xa (relu-able); remaining CIN-CA from xb (skip)
// ---------------------------------------------------------------------------
template<int CIN, int CA, bool RELU_A>
__global__ __launch_bounds__(320)
void gemm_kernel(const float* __restrict__ xa, const float* __restrict__ xb,
                 const float* __restrict__ W, const float* __restrict__ root,
                 const float* __restrict__ bias,
                 float* __restrict__ Y, float* __restrict__ agg, int n_nodes)
{
    const int c = threadIdx.x;          // 0..319

    // Load this thread's weight column into registers.
    float w[CIN];
    if (c < CKOUT) {
        const int k = c >> 5, cc = c & 31;
        #pragma unroll
        for (int i = 0; i < CIN; i++) w[i] = W[(k * CIN + i) * 32 + cc];
    } else {
        const int cc = c - CKOUT;
        #pragma unroll
        for (int i = 0; i < CIN; i++) w[i] = root[i * 32 + cc];
    }
    const float bv = (c >= CKOUT) ? bias[c - CKOUT] : 0.0f;

    __shared__ float xsh[CIN][8];       // [input channel][node-in-tile]

    for (int n0 = blockIdx.x * 8; n0 < n_nodes; n0 += gridDim.x * 8) {
        // Stage 8-node input tile (transposed) into shared.
        for (int j = c; j < CIN * 8; j += 320) {
            const int nn = j / CIN;     // CIN is constexpr pow2 -> shift
            const int i  = j - nn * CIN;
            const int n  = n0 + nn;
            float v = 0.0f;
            if (n < n_nodes) {
                if (CA < CIN && i >= CA) {
                    v = xb[n * (CIN - CA) + (i - CA)];
                } else {
                    v = xa[n * CA + i];
                    if (RELU_A) v = fmaxf(v, 0.0f);
                }
            }
            xsh[i][nn] = v;
        }
        __syncthreads();

        float acc[8] = {0.f, 0.f, 0.f, 0.f, 0.f, 0.f, 0.f, 0.f};
        #pragma unroll
        for (int i = 0; i < CIN; i++) {
            const float wv = w[i];
            const float4 a = *reinterpret_cast<const float4*>(&xsh[i][0]);
            const float4 b = *reinterpret_cast<const float4*>(&xsh[i][4]);
            acc[0] += wv * a.x; acc[1] += wv * a.y;
            acc[2] += wv * a.z; acc[3] += wv * a.w;
            acc[4] += wv * b.x; acc[5] += wv * b.y;
            acc[6] += wv * b.z; acc[7] += wv * b.w;
        }

        #pragma unroll
        for (int nn = 0; nn < 8; nn++) {
            const int n = n0 + nn;
            if (n < n_nodes) {
                if (c < CKOUT) Y[(size_t)n * CKOUT + c] = acc[nn];
                else           agg[(size_t)n * 32 + (c - CKOUT)] = acc[nn] + bv;
            }
        }
        __syncthreads();
    }
}

// ---------------------------------------------------------------------------
// Edge kernel: one warp per edge, lane = output channel.
// B-spline basis (degree 2, open, kernel 3): q(t) = [.5(1-t)^2, -t^2+t+.5, .5t^2]
// B[e, 3*k1+k0] = q1[k1] * q0[k0]
// ---------------------------------------------------------------------------
__global__ __launch_bounds__(256)
void edge_kernel(const int* __restrict__ ei, const float* __restrict__ pseudo,
                 const float* __restrict__ Y, float* __restrict__ agg,
                 int n_edges, int n_nodes)
{
    const int e    = (int)((blockIdx.x * 256u + threadIdx.x) >> 5);
    const int lane = threadIdx.x & 31;
    if (e >= n_edges) return;

    const int src = ei[e];
    const int dst = ei[n_edges + e];
    // Defensive: if index interpretation is ever wrong, produce a wrong answer
    // (diagnosable rel_err) instead of an illegal access.
    if ((unsigned)src >= (unsigned)n_nodes || (unsigned)dst >= (unsigned)n_nodes) return;

    const float p0 = pseudo[2 * e];
    const float p1 = pseudo[2 * e + 1];

    const float q00 = 0.5f * (1.0f - p0) * (1.0f - p0);
    const float q01 = -p0 * p0 + p0 + 0.5f;
    const float q02 = 0.5f * p0 * p0;
    const float q10 = 0.5f * (1.0f - p1) * (1.0f - p1);
    const float q11 = -p1 * p1 + p1 + 0.5f;
    const float q12 = 0.5f * p1 * p1;

    const float* y = Y + (size_t)src * CKOUT + lane;
    float acc;
    acc  = (q10 * q00) * y[0 * 32];
    acc += (q10 * q01) * y[1 * 32];
    acc += (q10 * q02) * y[2 * 32];
    acc += (q11 * q00) * y[3 * 32];
    acc += (q11 * q01) * y[4 * 32];
    acc += (q11 * q02) * y[5 * 32];
    acc += (q12 * q00) * y[6 * 32];
    acc += (q12 * q01) * y[7 * 32];
    acc += (q12 * q02) * y[8 * 32];

    atomicAdd(&agg[(size_t)dst * 32 + lane], acc);   // -> RED.E.ADD.F32
}

__global__ void relu_kernel(float* __restrict__ d, int n)
{
    const int i = blockIdx.x * blockDim.x + threadIdx.x;
    if (i < n) d[i] = fmaxf(d[i], 0.0f);
}

// ---------------------------------------------------------------------------
extern "C" void kernel_launch(void* const* d_in, const int* in_sizes, int n_in,
                              void* d_out, int out_size)
{
    const float* x      = (const float*)d_in[0];
    const int*   ei     = (const int*)d_in[1];     // int64 in ref -> int32 in harness
    const float* pseudo = (const float*)d_in[2];
    const float* skip   = (const float*)d_in[3];
    const float* W1     = (const float*)d_in[4];
    const float* root1  = (const float*)d_in[5];
    const float* b1     = (const float*)d_in[6];
    const float* W2     = (const float*)d_in[7];
    const float* root2  = (const float*)d_in[8];
    const float* b2     = (const float*)d_in[9];

    const int N = in_sizes[0] / 64;
    const int E = in_sizes[1] / 2;
    float* out = (float*)d_out;

    float *Y, *agg1, *agg2;
    cudaGetSymbolAddress((void**)&Y,    g_Y);
    cudaGetSymbolAddress((void**)&agg1, g_agg1);
    cudaGetSymbolAddress((void**)&agg2, g_agg2);

    const int gemm_grid = (N + 7) / 8;
    const int edge_grid = (E * 32 + 255) / 256;

    // Layer 1: x[N,64] -> agg1
    gemm_kernel<64, 64, false><<<gemm_grid, 320>>>(x, nullptr, W1, root1, b1, Y, agg1, N);
    edge_kernel<<<edge_grid, 256>>>(ei, pseudo, Y, agg1, E, N);

    // Layer 2: concat(relu(agg1), skip)[N,64] -> agg2   (same W1/root1/b1)
    gemm_kernel<64, 32, true><<<gemm_grid, 320>>>(agg1, skip, W1, root1, b1, Y, agg2, N);
    edge_kernel<<<edge_grid, 256>>>(ei, pseudo, Y, agg2, E, N);

    // Layer 3: relu(agg2)[N,32] -> d_out
    gemm_kernel<32, 32, true><<<gemm_grid, 320>>>(agg2, nullptr, W2, root2, b2, Y, out, N);
    edge_kernel<<<edge_grid, 256>>>(ei, pseudo, Y, out, E, N);

    // Final relu in place on d_out.
    relu_kernel<<<(N * 32 + 255) / 256, 256>>>(out, N * 32);
}

// round 3
// speedup vs baseline: 1.0461x; 1.0461x over previous
#include <cuda_runtime.h>

// ---------------------------------------------------------------------------
// MeshUpConv: 3x SplineConv (kernel 3x3, degree 2, open spline) on GB300.
//
//   per layer: GEMM  Y[n, k*32+c] = sum_i x[n,i] * W[k,i,c]   (+ self term)
//   edge pass: acc_c = sum_k B[e,k] * Y[src, k*32+c];  RED.add agg[dst,c]
//
// R2 -> R3 changes:
//   * GEMM inner loop uses packed fma.rn.f32x2 (2x FP32 rate), 16-node tile.
//   * Edge kernel: 8 lanes/edge, float4 per lane -> LDG.128 gathers and one
//     red.global.add.v4.f32 per lane (4x fewer LSU requests).
// ---------------------------------------------------------------------------

#define NMAX 50000
#define CKOUT 288          // K * C_OUT = 9 * 32

__device__ float g_Y[(size_t)NMAX * CKOUT];
__device__ float g_agg1[(size_t)NMAX * 32];
__device__ float g_agg2[(size_t)NMAX * 32];

// f32x2 packed helpers (bits live in a 64-bit reg pair; reinterpret is free).
__device__ __forceinline__ double ffma2(double a, double b, double c) {
    double d;
    asm("fma.rn.f32x2 %0, %1, %2, %3;" : "=d"(d) : "d"(a), "d"(b), "d"(c));
    return d;
}
__device__ __forceinline__ double pack2(float x) {
    double r;
    asm("mov.b64 %0, {%1, %1};" : "=d"(r) : "f"(x));
    return r;
}
__device__ __forceinline__ void unpack2(double v, float& lo, float& hi) {
    asm("mov.b64 {%0, %1}, %2;" : "=f"(lo), "=f"(hi) : "d"(v));
}

// ---------------------------------------------------------------------------
// GEMM: 320 threads = 320 output columns (288 Y + 32 self). W column in regs,
// 16-node x tile staged transposed in shared, broadcast LDS.128 reads,
// packed f32x2 FMA inner loop.
// ---------------------------------------------------------------------------
template<int CIN, int CA, bool RELU_A>
__global__ __launch_bounds__(320)
void gemm_kernel(const float* __restrict__ xa, const float* __restrict__ xb,
                 const float* __restrict__ W, const float* __restrict__ root,
                 const float* __restrict__ bias,
                 float* __restrict__ Y, float* __restrict__ agg, int n_nodes)
{
    const int c = threadIdx.x;          // 0..319

    float w[CIN];
    if (c < CKOUT) {
        const int k = c >> 5, cc = c & 31;
        #pragma unroll
        for (int i = 0; i < CIN; i++) w[i] = W[(k * CIN + i) * 32 + cc];
    } else {
        const int cc = c - CKOUT;
        #pragma unroll
        for (int i = 0; i < CIN; i++) w[i] = root[i * 32 + cc];
    }
    const float bv = (c >= CKOUT) ? bias[c - CKOUT] : 0.0f;

    __shared__ __align__(16) float xsh[CIN][16];   // [in-channel][node-in-tile]

    for (int n0 = blockIdx.x * 16; n0 < n_nodes; n0 += gridDim.x * 16) {
        // Stage 16-node input tile (transposed; relu/concat fused).
        for (int j = c; j < CIN * 16; j += 320) {
            const int nn = j / CIN;
            const int i  = j - nn * CIN;
            const int n  = n0 + nn;
            float v = 0.0f;
            if (n < n_nodes) {
                if (CA < CIN && i >= CA) {
                    v = xb[n * (CIN - CA) + (i - CA)];
                } else {
                    v = xa[n * CA + i];
                    if (RELU_A) v = fmaxf(v, 0.0f);
                }
            }
            xsh[i][nn] = v;
        }
        __syncthreads();

        double acc[8];                   // 8 x f32x2 = 16 node results
        #pragma unroll
        for (int j = 0; j < 8; j++) acc[j] = 0.0;

        #pragma unroll
        for (int i = 0; i < CIN; i++) {
            const double w2 = pack2(w[i]);
            const double2* xs = reinterpret_cast<const double2*>(&xsh[i][0]);
            const double2 p0 = xs[0], p1 = xs[1], p2 = xs[2], p3 = xs[3];
            acc[0] = ffma2(w2, p0.x, acc[0]);
            acc[1] = ffma2(w2, p0.y, acc[1]);
            acc[2] = ffma2(w2, p1.x, acc[2]);
            acc[3] = ffma2(w2, p1.y, acc[3]);
            acc[4] = ffma2(w2, p2.x, acc[4]);
            acc[5] = ffma2(w2, p2.y, acc[5]);
            acc[6] = ffma2(w2, p3.x, acc[6]);
            acc[7] = ffma2(w2, p3.y, acc[7]);
        }

        #pragma unroll
        for (int j = 0; j < 8; j++) {
            float lo, hi;
            unpack2(acc[j], lo, hi);
            const int na = n0 + 2 * j;
            const int nb = na + 1;
            if (na < n_nodes) {
                if (c < CKOUT) Y[(size_t)na * CKOUT + c] = lo;
                else           agg[(size_t)na * 32 + (c - CKOUT)] = lo + bv;
            }
            if (nb < n_nodes) {
                if (c < CKOUT) Y[(size_t)nb * CKOUT + c] = hi;
                else           agg[(size_t)nb * 32 + (c - CKOUT)] = hi + bv;
            }
        }
        __syncthreads();
    }
}

// ---------------------------------------------------------------------------
// Edge kernel: 8 lanes per edge, 4 channels per lane (float4).
// 9 LDG.128 gathers + 1 red.global.add.v4.f32 per lane.
// Basis (degree 2, open, kernel 3): q(t) = [.5(1-t)^2, -t^2+t+.5, .5t^2]
// ---------------------------------------------------------------------------
__global__ __launch_bounds__(256)
void edge_kernel(const int* __restrict__ ei, const float* __restrict__ pseudo,
                 const float* __restrict__ Y, float* __restrict__ agg,
                 int n_edges, int n_nodes)
{
    const int t    = blockIdx.x * 256 + threadIdx.x;
    const int e    = t >> 3;            // 8 lanes per edge
    const int sub  = t & 7;             // channel group: channels [4*sub, 4*sub+4)
    if (e >= n_edges) return;

    const int src = ei[e];
    const int dst = ei[n_edges + e];
    if ((unsigned)src >= (unsigned)n_nodes || (unsigned)dst >= (unsigned)n_nodes) return;

    const float2 p = reinterpret_cast<const float2*>(pseudo)[e];

    const float q00 = 0.5f * (1.0f - p.x) * (1.0f - p.x);
    const float q01 = -p.x * p.x + p.x + 0.5f;
    const float q02 = 0.5f * p.x * p.x;
    const float q10 = 0.5f * (1.0f - p.y) * (1.0f - p.y);
    const float q11 = -p.y * p.y + p.y + 0.5f;
    const float q12 = 0.5f * p.y * p.y;

    const float b0 = q10 * q00, b1 = q10 * q01, b2 = q10 * q02;
    const float b3 = q11 * q00, b4 = q11 * q01, b5 = q11 * q02;
    const float b6 = q12 * q00, b7 = q12 * q01, b8 = q12 * q02;

    const float4* y = reinterpret_cast<const float4*>(Y + (size_t)src * CKOUT + sub * 4);
    // stride between k-slices: 32 floats = 8 float4
    const float4 y0 = y[0*8], y1 = y[1*8], y2 = y[2*8];
    const float4 y3 = y[3*8], y4 = y[4*8], y5 = y[5*8];
    const float4 y6 = y[6*8], y7 = y[7*8], y8 = y[8*8];

    float4 a;
    a.x = b0*y0.x + b1*y1.x + b2*y2.x + b3*y3.x + b4*y4.x + b5*y5.x + b6*y6.x + b7*y7.x + b8*y8.x;
    a.y = b0*y0.y + b1*y1.y + b2*y2.y + b3*y3.y + b4*y4.y + b5*y5.y + b6*y6.y + b7*y7.y + b8*y8.y;
    a.z = b0*y0.z + b1*y1.z + b2*y2.z + b3*y3.z + b4*y4.z + b5*y5.z + b6*y6.z + b7*y7.z + b8*y8.z;
    a.w = b0*y0.w + b1*y1.w + b2*y2.w + b3*y3.w + b4*y4.w + b5*y5.w + b6*y6.w + b7*y7.w + b8*y8.w;

    float* dp = agg + (size_t)dst * 32 + sub * 4;
    asm volatile("red.global.add.v4.f32 [%0], {%1, %2, %3, %4};"
                 :: "l"(dp), "f"(a.x), "f"(a.y), "f"(a.z), "f"(a.w) : "memory");
}

__global__ void relu_kernel(float* __restrict__ d, int n)
{
    const int i = blockIdx.x * blockDim.x + threadIdx.x;
    if (i < n) d[i] = fmaxf(d[i], 0.0f);
}

// ---------------------------------------------------------------------------
extern "C" void kernel_launch(void* const* d_in, const int* in_sizes, int n_in,
                              void* d_out, int out_size)
{
    const float* x      = (const float*)d_in[0];
    const int*   ei     = (const int*)d_in[1];     // int64 in ref -> int32 in harness
    const float* pseudo = (const float*)d_in[2];
    const float* skip   = (const float*)d_in[3];
    const float* W1     = (const float*)d_in[4];
    const float* root1  = (const float*)d_in[5];
    const float* b1     = (const float*)d_in[6];
    const float* W2     = (const float*)d_in[7];
    const float* root2  = (const float*)d_in[8];
    const float* b2     = (const float*)d_in[9];

    const int N = in_sizes[0] / 64;
    const int E = in_sizes[1] / 2;
    float* out = (float*)d_out;

    float *Y, *agg1, *agg2;
    cudaGetSymbolAddress((void**)&Y,    g_Y);
    cudaGetSymbolAddress((void**)&agg1, g_agg1);
    cudaGetSymbolAddress((void**)&agg2, g_agg2);

    const int gemm_grid = (N + 15) / 16;
    const int edge_grid = (E * 8 + 255) / 256;

    // Layer 1: x[N,64] -> agg1
    gemm_kernel<64, 64, false><<<gemm_grid, 320>>>(x, nullptr, W1, root1, b1, Y, agg1, N);
    edge_kernel<<<edge_grid, 256>>>(ei, pseudo, Y, agg1, E, N);

    // Layer 2: concat(relu(agg1), skip)[N,64] -> agg2   (same W1/root1/b1)
    gemm_kernel<64, 32, true><<<gemm_grid, 320>>>(agg1, skip, W1, root1, b1, Y, agg2, N);
    edge_kernel<<<edge_grid, 256>>>(ei, pseudo, Y, agg2, E, N);

    // Layer 3: relu(agg2)[N,32] -> d_out
    gemm_kernel<32, 32, true><<<gemm_grid, 320>>>(agg2, nullptr, W2, root2, b2, Y, out, N);
    edge_kernel<<<edge_grid, 256>>>(ei, pseudo, Y, out, E, N);

    relu_kernel<<<(N * 32 + 255) / 256, 256>>>(out, N * 32);
}

// round 4
// speedup vs baseline: 1.2988x; 1.2415x over previous
#include <cuda_runtime.h>

// ---------------------------------------------------------------------------
// MeshUpConv: 3x SplineConv (kernel 3x3, degree 2, open spline) on GB300.
//
//   per layer: GEMM  Y[n, k*32+c] = sum_i x[n,i] * W[k,i,c]   (+ self term)
//   edge pass: acc_c = sum_k B[e,k] * Y[src, k*32+c];  RED.add agg[dst,c]
//
// R3 -> R4: persistent GEMM blocks (grid=296, w loaded once, grid-stride over
// node tiles), double-buffered smem staging (prefetch-to-regs overlaps LDG
// with FMA), padded smem (stride 20) for fewer STS bank conflicts.
// Edge kernel unchanged (at L2-byte roofline).
// ---------------------------------------------------------------------------

#define NMAX 50000
#define CKOUT 288          // K * C_OUT = 9 * 32

__device__ float g_Y[(size_t)NMAX * CKOUT];
__device__ float g_agg1[(size_t)NMAX * 32];
__device__ float g_agg2[(size_t)NMAX * 32];

// f32x2 packed helpers.
__device__ __forceinline__ double ffma2(double a, double b, double c) {
    double d;
    asm("fma.rn.f32x2 %0, %1, %2, %3;" : "=d"(d) : "d"(a), "d"(b), "d"(c));
    return d;
}
__device__ __forceinline__ double pack2(float x) {
    double r;
    asm("mov.b64 %0, {%1, %1};" : "=d"(r) : "f"(x));
    return r;
}
__device__ __forceinline__ void unpack2(double v, float& lo, float& hi) {
    asm("mov.b64 {%0, %1}, %2;" : "=f"(lo), "=f"(hi) : "d"(v));
}

#define XPAD 20            // floats per smem row: 16 data + 4 pad (16B-aligned)

// ---------------------------------------------------------------------------
// Persistent GEMM: 320 threads = 320 output columns (288 Y + 32 self).
// W column in regs (loaded once per block), grid-stride over 16-node tiles,
// double-buffered transposed x tile in shared, f32x2 FMA inner loop.
// ---------------------------------------------------------------------------
template<int CIN, int CA, bool RELU_A>
__global__ __launch_bounds__(320)
void gemm_kernel(const float* __restrict__ xa, const float* __restrict__ xb,
                 const float* __restrict__ W, const float* __restrict__ root,
                 const float* __restrict__ bias,
                 float* __restrict__ Y, float* __restrict__ agg, int n_nodes)
{
    const int c = threadIdx.x;          // 0..319
    constexpr int NPF = (CIN * 16 + 319) / 320;   // prefetch regs per thread

    float w[CIN];
    if (c < CKOUT) {
        const int k = c >> 5, cc = c & 31;
        #pragma unroll
        for (int i = 0; i < CIN; i++) w[i] = W[(k * CIN + i) * 32 + cc];
    } else {
        const int cc = c - CKOUT;
        #pragma unroll
        for (int i = 0; i < CIN; i++) w[i] = root[i * 32 + cc];
    }
    const float bv = (c >= CKOUT) ? bias[c - CKOUT] : 0.0f;

    __shared__ __align__(16) float xsh[2][CIN][XPAD];

    const int ntiles = (n_nodes + 15) >> 4;

    // Fetch element j (0..CIN*16) of tile t, with relu/concat fused.
    auto fetch = [&](int t, int j) -> float {
        const int nn = j / CIN;         // CIN is pow2 -> shift
        const int i  = j - nn * CIN;
        const int n  = t * 16 + nn;
        float v = 0.0f;
        if (n < n_nodes) {
            if (CA < CIN && i >= CA) {
                v = xb[n * (CIN - CA) + (i - CA)];
            } else {
                v = xa[n * CA + i];
                if (RELU_A) v = fmaxf(v, 0.0f);
            }
        }
        return v;
    };

    int t = blockIdx.x;
    // Prologue: stage first tile into buffer 0.
    if (t < ntiles) {
        #pragma unroll
        for (int k = 0; k < NPF; k++) {
            const int j = c + k * 320;
            if (j < CIN * 16) {
                const int nn = j / CIN, i = j - nn * CIN;
                xsh[0][i][nn] = fetch(t, j);
            }
        }
    }
    __syncthreads();

    int buf = 0;
    for (; t < ntiles; t += gridDim.x, buf ^= 1) {
        const int tn = t + gridDim.x;

        // Prefetch next tile into registers (overlaps with compute below).
        float pf[NPF];
        if (tn < ntiles) {
            #pragma unroll
            for (int k = 0; k < NPF; k++) {
                const int j = c + k * 320;
                pf[k] = (j < CIN * 16) ? fetch(tn, j) : 0.0f;
            }
        }

        // Compute 16 node results from current buffer.
        double acc[8];
        #pragma unroll
        for (int j = 0; j < 8; j++) acc[j] = 0.0;

        #pragma unroll
        for (int i = 0; i < CIN; i++) {
            const double w2 = pack2(w[i]);
            const double2* xs = reinterpret_cast<const double2*>(&xsh[buf][i][0]);
            const double2 p0 = xs[0], p1 = xs[1], p2 = xs[2], p3 = xs[3];
            acc[0] = ffma2(w2, p0.x, acc[0]);
            acc[1] = ffma2(w2, p0.y, acc[1]);
            acc[2] = ffma2(w2, p1.x, acc[2]);
            acc[3] = ffma2(w2, p1.y, acc[3]);
            acc[4] = ffma2(w2, p2.x, acc[4]);
            acc[5] = ffma2(w2, p2.y, acc[5]);
            acc[6] = ffma2(w2, p3.x, acc[6]);
            acc[7] = ffma2(w2, p3.y, acc[7]);
        }

        const int n0 = t * 16;
        #pragma unroll
        for (int j = 0; j < 8; j++) {
            float lo, hi;
            unpack2(acc[j], lo, hi);
            const int na = n0 + 2 * j;
            const int nb = na + 1;
            if (na < n_nodes) {
                if (c < CKOUT) Y[(size_t)na * CKOUT + c] = lo;
                else           agg[(size_t)na * 32 + (c - CKOUT)] = lo + bv;
            }
            if (nb < n_nodes) {
                if (c < CKOUT) Y[(size_t)nb * CKOUT + c] = hi;
                else           agg[(size_t)nb * 32 + (c - CKOUT)] = hi + bv;
            }
        }

        __syncthreads();   // everyone done reading xsh[buf] (and prior buf^1)
        if (tn < ntiles) {
            #pragma unroll
            for (int k = 0; k < NPF; k++) {
                const int j = c + k * 320;
                if (j < CIN * 16) {
                    const int nn = j / CIN, i = j - nn * CIN;
                    xsh[buf ^ 1][i][nn] = pf[k];
                }
            }
        }
        __syncthreads();   // next tile staged
    }
}

// ---------------------------------------------------------------------------
// Edge kernel: 8 lanes per edge, 4 channels per lane (float4).
// 9 LDG.128 gathers + 1 red.global.add.v4.f32 per lane.  (L2-byte bound.)
// ---------------------------------------------------------------------------
__global__ __launch_bounds__(256)
void edge_kernel(const int* __restrict__ ei, const float* __restrict__ pseudo,
                 const float* __restrict__ Y, float* __restrict__ agg,
                 int n_edges, int n_nodes)
{
    const int t    = blockIdx.x * 256 + threadIdx.x;
    const int e    = t >> 3;
    const int sub  = t & 7;
    if (e >= n_edges) return;

    const int src = ei[e];
    const int dst = ei[n_edges + e];
    if ((unsigned)src >= (unsigned)n_nodes || (unsigned)dst >= (unsigned)n_nodes) return;

    const float2 p = reinterpret_cast<const float2*>(pseudo)[e];

    const float q00 = 0.5f * (1.0f - p.x) * (1.0f - p.x);
    const float q01 = -p.x * p.x + p.x + 0.5f;
    const float q02 = 0.5f * p.x * p.x;
    const float q10 = 0.5f * (1.0f - p.y) * (1.0f - p.y);
    const float q11 = -p.y * p.y + p.y + 0.5f;
    const float q12 = 0.5f * p.y * p.y;

    const float b0 = q10 * q00, b1 = q10 * q01, b2 = q10 * q02;
    const float b3 = q11 * q00, b4 = q11 * q01, b5 = q11 * q02;
    const float b6 = q12 * q00, b7 = q12 * q01, b8 = q12 * q02;

    const float4* y = reinterpret_cast<const float4*>(Y + (size_t)src * CKOUT + sub * 4);
    const float4 y0 = y[0*8], y1 = y[1*8], y2 = y[2*8];
    const float4 y3 = y[3*8], y4 = y[4*8], y5 = y[5*8];
    const float4 y6 = y[6*8], y7 = y[7*8], y8 = y[8*8];

    float4 a;
    a.x = b0*y0.x + b1*y1.x + b2*y2.x + b3*y3.x + b4*y4.x + b5*y5.x + b6*y6.x + b7*y7.x + b8*y8.x;
    a.y = b0*y0.y + b1*y1.y + b2*y2.y + b3*y3.y + b4*y4.y + b5*y5.y + b6*y6.y + b7*y7.y + b8*y8.y;
    a.z = b0*y0.z + b1*y1.z + b2*y2.z + b3*y3.z + b4*y4.z + b5*y5.z + b6*y6.z + b7*y7.z + b8*y8.z;
    a.w = b0*y0.w + b1*y1.w + b2*y2.w + b3*y3.w + b4*y4.w + b5*y5.w + b6*y6.w + b7*y7.w + b8*y8.w;

    float* dp = agg + (size_t)dst * 32 + sub * 4;
    asm volatile("red.global.add.v4.f32 [%0], {%1, %2, %3, %4};"
                 :: "l"(dp), "f"(a.x), "f"(a.y), "f"(a.z), "f"(a.w) : "memory");
}

__global__ void relu_kernel(float* __restrict__ d, int n)
{
    const int i = blockIdx.x * blockDim.x + threadIdx.x;
    if (i < n) d[i] = fmaxf(d[i], 0.0f);
}

// ---------------------------------------------------------------------------
extern "C" void kernel_launch(void* const* d_in, const int* in_sizes, int n_in,
                              void* d_out, int out_size)
{
    const float* x      = (const float*)d_in[0];
    const int*   ei     = (const int*)d_in[1];     // int64 in ref -> int32 in harness
    const float* pseudo = (const float*)d_in[2];
    const float* skip   = (const float*)d_in[3];
    const float* W1     = (const float*)d_in[4];
    const float* root1  = (const float*)d_in[5];
    const float* b1     = (const float*)d_in[6];
    const float* W2     = (const float*)d_in[7];
    const float* root2  = (const float*)d_in[8];
    const float* b2     = (const float*)d_in[9];

    const int N = in_sizes[0] / 64;
    const int E = in_sizes[1] / 2;
    float* out = (float*)d_out;

    float *Y, *agg1, *agg2;
    cudaGetSymbolAddress((void**)&Y,    g_Y);
    cudaGetSymbolAddress((void**)&agg1, g_agg1);
    cudaGetSymbolAddress((void**)&agg2, g_agg2);

    const int gemm_grid = 296;          // 2 persistent blocks per SM
    const int edge_grid = (E * 8 + 255) / 256;

    // Layer 1: x[N,64] -> agg1
    gemm_kernel<64, 64, false><<<gemm_grid, 320>>>(x, nullptr, W1, root1, b1, Y, agg1, N);
    edge_kernel<<<edge_grid, 256>>>(ei, pseudo, Y, agg1, E, N);

    // Layer 2: concat(relu(agg1), skip)[N,64] -> agg2   (same W1/root1/b1)
    gemm_kernel<64, 32, true><<<gemm_grid, 320>>>(agg1, skip, W1, root1, b1, Y, agg2, N);
    edge_kernel<<<edge_grid, 256>>>(ei, pseudo, Y, agg2, E, N);

    // Layer 3: relu(agg2)[N,32] -> d_out
    gemm_kernel<32, 32, true><<<gemm_grid, 320>>>(agg2, nullptr, W2, root2, b2, Y, out, N);
    edge_kernel<<<edge_grid, 256>>>(ei, pseudo, Y, out, E, N);

    relu_kernel<<<(N * 32 + 255) / 256, 256>>>(out, N * 32);
}

// round 6
// speedup vs baseline: 1.6591x; 1.2774x over previous
#include <cuda_runtime.h>
#include <cuda_bf16.h>
#include <cstdint>

// ---------------------------------------------------------------------------
// MeshUpConv: 3x SplineConv (kernel 3x3, degree 2, open spline) on GB300.
//
//   per layer: GEMM  Y[n, k*32+c] = sum_i x[n,i] * W[k,i,c]   (+ self cols)
//   edge pass: acc_c = sum_k B[e,k] * Y[src, k*32+c];  RED.add agg[dst,c]
//
// R5 -> R6: harness PTX target is compute_103 (no 'a') -> tcgen05 unavailable.
// GEMM now uses warp-level mma.sync.m16n8k16 bf16 (baseline PTX feature,
// legacy HMMA on Blackwell) with bf16x3 split precision:
//   X = Xh + Xl, W = Wh + Wl;  D = Xh*Wh + Xh*Wl + Xl*Wh  (fp32 accum).
// Persistent 148 CTAs x 512 threads; B staged once per CTA; A tile per 64
// nodes with relu/concat fused. Edge kernel unchanged (L2-byte bound).
// ---------------------------------------------------------------------------

#define NMAX  50000
#define CKOUT 288          // K * C_OUT = 9 * 32
#define NCOLS 320          // 288 Y cols + 32 self cols

__device__ float g_Y[(size_t)NMAX * CKOUT];
__device__ float g_agg1[(size_t)NMAX * 32];
__device__ float g_agg2[(size_t)NMAX * 32];

// ---- helpers --------------------------------------------------------------
__device__ __forceinline__ uint32_t pack_bf16(float a, float b) {
    __nv_bfloat162 t = __floats2bfloat162_rn(a, b);
    return *reinterpret_cast<uint32_t*>(&t);
}
__device__ __forceinline__ void split_hl(float v, float& h, float& l) {
    __nv_bfloat16 bh = __float2bfloat16_rn(v);
    h = __bfloat162float(bh);
    l = v - h;
}
__device__ __forceinline__ void mma_bf16(float* c,
                                         uint32_t a0, uint32_t a1, uint32_t a2, uint32_t a3,
                                         uint32_t b0, uint32_t b1) {
    asm("mma.sync.aligned.m16n8k16.row.col.f32.bf16.bf16.f32 "
        "{%0,%1,%2,%3}, {%4,%5,%6,%7}, {%8,%9}, {%0,%1,%2,%3};"
        : "+f"(c[0]), "+f"(c[1]), "+f"(c[2]), "+f"(c[3])
        : "r"(a0), "r"(a1), "r"(a2), "r"(a3), "r"(b0), "r"(b1));
}

// SMEM layout (bytes). Rows padded to 34 words (136B) -> few bank conflicts.
// A: 64 rows x 32 kpairs; B: 320 rows (out cols) x 32 kpairs; each hi & lo.
#define ASTR 34
#define SM_BIAS 0
#define SM_A_HI 128
#define SM_A_LO (SM_A_HI + 64 * ASTR * 4)        //  8832
#define SM_B_HI (SM_A_LO + 64 * ASTR * 4)        // 17536
#define SM_B_LO (SM_B_HI + 320 * ASTR * 4)       // 61056
#define SMEM_BYTES (SM_B_LO + 320 * ASTR * 4)    // 104576

// ---------------------------------------------------------------------------
// mma.sync GEMM: per 64-node tile, D[64, 320] = A[64,64] @ Bw[64,320].
//   CA: channels from xa (relu if RELU_A); CB: channels from xb; rest zero.
//   CIN_W: W/root depth (64 or 32). KSTEPS = CIN_W/16.
// Warp grid 4(M) x 4(N): warp = 16 rows x 80 cols = 1 m-tile x 10 n-tiles.
// ---------------------------------------------------------------------------
template<int CA, int CB, bool RELU_A, int CIN_W>
__global__ __launch_bounds__(512)
void gemm_mma(const float* __restrict__ xa, const float* __restrict__ xb,
              const float* __restrict__ W, const float* __restrict__ root,
              const float* __restrict__ bias,
              float* __restrict__ Y, float* __restrict__ agg, int n_nodes)
{
    extern __shared__ __align__(16) char smem[];
    uint32_t* Ah = reinterpret_cast<uint32_t*>(smem + SM_A_HI);
    uint32_t* Al = reinterpret_cast<uint32_t*>(smem + SM_A_LO);
    uint32_t* Bh = reinterpret_cast<uint32_t*>(smem + SM_B_HI);
    uint32_t* Bl = reinterpret_cast<uint32_t*>(smem + SM_B_LO);
    float*    bs = reinterpret_cast<float*>(smem + SM_BIAS);

    const int tid    = threadIdx.x;
    const int wid    = tid >> 5;
    const int lane   = tid & 31;
    const int warp_m = wid >> 2;        // 0..3 -> rows [16*warp_m, +16)
    const int warp_n = wid & 3;         // 0..3 -> cols [80*warp_n, +80)
    constexpr int KSTEPS = CIN_W / 16;

    // ---- Stage B once per CTA: row r = output col, 32 k-pairs (pad to 64 k).
    for (int idx = tid; idx < NCOLS * 32; idx += 512) {
        const int r  = idx >> 5;
        const int kp = idx & 31;
        const int i0 = 2 * kp, i1 = i0 + 1;
        float v0 = 0.0f, v1 = 0.0f;
        if (i0 < CIN_W) {
            if (r < CKOUT) {
                const int kk = r >> 5, cc = r & 31;
                v0 = W[(kk * CIN_W + i0) * 32 + cc];
                v1 = W[(kk * CIN_W + i1) * 32 + cc];
            } else {
                v0 = root[i0 * 32 + (r - CKOUT)];
                v1 = root[i1 * 32 + (r - CKOUT)];
            }
        }
        float h0, l0, h1, l1;
        split_hl(v0, h0, l0); split_hl(v1, h1, l1);
        Bh[r * ASTR + kp] = pack_bf16(h0, h1);
        Bl[r * ASTR + kp] = pack_bf16(l0, l1);
    }
    if (tid < 32) bs[tid] = bias[tid];
    __syncthreads();

    const int ntiles = (n_nodes + 63) >> 6;

    for (int t = blockIdx.x; t < ntiles; t += gridDim.x) {
        const int n0 = t << 6;

        // ---- Stage A tile: 64 rows x 32 k-pairs, hi/lo, relu/concat fused.
        for (int idx = tid; idx < 64 * 32; idx += 512) {
            const int row = idx >> 5;
            const int kp  = idx & 31;
            const int n   = n0 + row;
            const int i0  = 2 * kp, i1 = i0 + 1;
            float v0 = 0.0f, v1 = 0.0f;
            if (n < n_nodes) {
                if (i0 < CA) {
                    v0 = xa[(size_t)n * CA + i0];
                    v1 = xa[(size_t)n * CA + i1];
                    if (RELU_A) { v0 = fmaxf(v0, 0.0f); v1 = fmaxf(v1, 0.0f); }
                } else if (CB > 0 && i0 < CA + CB) {
                    v0 = xb[(size_t)n * CB + (i0 - CA)];
                    v1 = xb[(size_t)n * CB + (i1 - CA)];
                }
            }
            float h0, l0, h1, l1;
            split_hl(v0, h0, l0); split_hl(v1, h1, l1);
            Ah[row * ASTR + kp] = pack_bf16(h0, h1);
            Al[row * ASTR + kp] = pack_bf16(l0, l1);
        }
        __syncthreads();

        // ---- Compute: acc[10 n-tiles][4]
        float acc[10][4];
        #pragma unroll
        for (int nt = 0; nt < 10; nt++)
            #pragma unroll
            for (int j = 0; j < 4; j++) acc[nt][j] = 0.0f;

        const int g   = warp_m * 16 + (lane >> 2);      // A row (and +8)
        const int lkp = lane & 3;                       // k-pair within step

        #pragma unroll
        for (int ks = 0; ks < KSTEPS; ks++) {
            const int kpb = ks * 8 + lkp;
            const uint32_t ah0 = Ah[g * ASTR + kpb];
            const uint32_t ah1 = Ah[(g + 8) * ASTR + kpb];
            const uint32_t ah2 = Ah[g * ASTR + kpb + 4];
            const uint32_t ah3 = Ah[(g + 8) * ASTR + kpb + 4];
            const uint32_t al0 = Al[g * ASTR + kpb];
            const uint32_t al1 = Al[(g + 8) * ASTR + kpb];
            const uint32_t al2 = Al[g * ASTR + kpb + 4];
            const uint32_t al3 = Al[(g + 8) * ASTR + kpb + 4];

            #pragma unroll
            for (int nt = 0; nt < 10; nt++) {
                const int nrow = warp_n * 80 + nt * 8 + (lane >> 2);
                const uint32_t bh0 = Bh[nrow * ASTR + kpb];
                const uint32_t bh1 = Bh[nrow * ASTR + kpb + 4];
                const uint32_t bl0 = Bl[nrow * ASTR + kpb];
                const uint32_t bl1 = Bl[nrow * ASTR + kpb + 4];
                mma_bf16(acc[nt], ah0, ah1, ah2, ah3, bh0, bh1);
                mma_bf16(acc[nt], ah0, ah1, ah2, ah3, bl0, bl1);
                mma_bf16(acc[nt], al0, al1, al2, al3, bh0, bh1);
            }
        }

        // ---- Epilogue: d0,d1 -> (row g, col0..col0+1); d2,d3 -> row g+8.
        const int r0 = n0 + g;
        const int r1 = r0 + 8;
        #pragma unroll
        for (int nt = 0; nt < 10; nt++) {
            const int col0 = warp_n * 80 + nt * 8 + 2 * (lane & 3);
            if (col0 < CKOUT) {
                if (r0 < n_nodes)
                    *reinterpret_cast<float2*>(Y + (size_t)r0 * CKOUT + col0)
                        = make_float2(acc[nt][0], acc[nt][1]);
                if (r1 < n_nodes)
                    *reinterpret_cast<float2*>(Y + (size_t)r1 * CKOUT + col0)
                        = make_float2(acc[nt][2], acc[nt][3]);
            } else {
                const int a = col0 - CKOUT;
                const float b0v = bs[a], b1v = bs[a + 1];
                if (r0 < n_nodes)
                    *reinterpret_cast<float2*>(agg + (size_t)r0 * 32 + a)
                        = make_float2(acc[nt][0] + b0v, acc[nt][1] + b1v);
                if (r1 < n_nodes)
                    *reinterpret_cast<float2*>(agg + (size_t)r1 * 32 + a)
                        = make_float2(acc[nt][2] + b0v, acc[nt][3] + b1v);
            }
        }
        __syncthreads();
    }
}

// ---------------------------------------------------------------------------
// Edge kernel: 8 lanes per edge, 4 channels per lane (float4).
// 9 LDG.128 gathers + 1 red.global.add.v4.f32 per lane.  (L2-byte bound.)
// ---------------------------------------------------------------------------
__global__ __launch_bounds__(256)
void edge_kernel(const int* __restrict__ ei, const float* __restrict__ pseudo,
                 const float* __restrict__ Y, float* __restrict__ agg,
                 int n_edges, int n_nodes)
{
    const int t    = blockIdx.x * 256 + threadIdx.x;
    const int e    = t >> 3;
    const int sub  = t & 7;
    if (e >= n_edges) return;

    const int src = ei[e];
    const int dst = ei[n_edges + e];
    if ((unsigned)src >= (unsigned)n_nodes || (unsigned)dst >= (unsigned)n_nodes) return;

    const float2 p = reinterpret_cast<const float2*>(pseudo)[e];

    const float q00 = 0.5f * (1.0f - p.x) * (1.0f - p.x);
    const float q01 = -p.x * p.x + p.x + 0.5f;
    const float q02 = 0.5f * p.x * p.x;
    const float q10 = 0.5f * (1.0f - p.y) * (1.0f - p.y);
    const float q11 = -p.y * p.y + p.y + 0.5f;
    const float q12 = 0.5f * p.y * p.y;

    const float b0 = q10 * q00, b1 = q10 * q01, b2 = q10 * q02;
    const float b3 = q11 * q00, b4 = q11 * q01, b5 = q11 * q02;
    const float b6 = q12 * q00, b7 = q12 * q01, b8 = q12 * q02;

    const float4* y = reinterpret_cast<const float4*>(Y + (size_t)src * CKOUT + sub * 4);
    const float4 y0 = y[0*8], y1 = y[1*8], y2 = y[2*8];
    const float4 y3 = y[3*8], y4 = y[4*8], y5 = y[5*8];
    const float4 y6 = y[6*8], y7 = y[7*8], y8 = y[8*8];

    float4 a;
    a.x = b0*y0.x + b1*y1.x + b2*y2.x + b3*y3.x + b4*y4.x + b5*y5.x + b6*y6.x + b7*y7.x + b8*y8.x;
    a.y = b0*y0.y + b1*y1.y + b2*y2.y + b3*y3.y + b4*y4.y + b5*y5.y + b6*y6.y + b7*y7.y + b8*y8.y;
    a.z = b0*y0.z + b1*y1.z + b2*y2.z + b3*y3.z + b4*y4.z + b5*y5.z + b6*y6.z + b7*y7.z + b8*y8.z;
    a.w = b0*y0.w + b1*y1.w + b2*y2.w + b3*y3.w + b4*y4.w + b5*y5.w + b6*y6.w + b7*y7.w + b8*y8.w;

    float* dp = agg + (size_t)dst * 32 + sub * 4;
    asm volatile("red.global.add.v4.f32 [%0], {%1, %2, %3, %4};"
                 :: "l"(dp), "f"(a.x), "f"(a.y), "f"(a.z), "f"(a.w) : "memory");
}

__global__ void relu_kernel(float* __restrict__ d, int n)
{
    const int i = blockIdx.x * blockDim.x + threadIdx.x;
    if (i < n) d[i] = fmaxf(d[i], 0.0f);
}

// ---------------------------------------------------------------------------
extern "C" void kernel_launch(void* const* d_in, const int* in_sizes, int n_in,
                              void* d_out, int out_size)
{
    const float* x      = (const float*)d_in[0];
    const int*   ei     = (const int*)d_in[1];     // int64 in ref -> int32 in harness
    const float* pseudo = (const float*)d_in[2];
    const float* skip   = (const float*)d_in[3];
    const float* W1     = (const float*)d_in[4];
    const float* root1  = (const float*)d_in[5];
    const float* b1     = (const float*)d_in[6];
    const float* W2     = (const float*)d_in[7];
    const float* root2  = (const float*)d_in[8];
    const float* b2     = (const float*)d_in[9];

    const int N = in_sizes[0] / 64;
    const int E = in_sizes[1] / 2;
    float* out = (float*)d_out;

    float *Y, *agg1, *agg2;
    cudaGetSymbolAddress((void**)&Y,    g_Y);
    cudaGetSymbolAddress((void**)&agg1, g_agg1);
    cudaGetSymbolAddress((void**)&agg2, g_agg2);

    cudaFuncSetAttribute(gemm_mma<64, 0,  false, 64>,
                         cudaFuncAttributeMaxDynamicSharedMemorySize, SMEM_BYTES);
    cudaFuncSetAttribute(gemm_mma<32, 32, true,  64>,
                         cudaFuncAttributeMaxDynamicSharedMemorySize, SMEM_BYTES);
    cudaFuncSetAttribute(gemm_mma<32, 0,  true,  32>,
                         cudaFuncAttributeMaxDynamicSharedMemorySize, SMEM_BYTES);

    const int gemm_grid = 148;
    const int edge_grid = (E * 8 + 255) / 256;

    // Layer 1: x[N,64] -> agg1
    gemm_mma<64, 0, false, 64><<<gemm_grid, 512, SMEM_BYTES>>>(x, nullptr, W1, root1, b1, Y, agg1, N);
    edge_kernel<<<edge_grid, 256>>>(ei, pseudo, Y, agg1, E, N);

    // Layer 2: concat(relu(agg1), skip)[N,64] -> agg2   (same W1/root1/b1)
    gemm_mma<32, 32, true, 64><<<gemm_grid, 512, SMEM_BYTES>>>(agg1, skip, W1, root1, b1, Y, agg2, N);
    edge_kernel<<<edge_grid, 256>>>(ei, pseudo, Y, agg2, E, N);

    // Layer 3: relu(agg2)[N,32] -> d_out  (K = 32 -> 2 k-steps)
    gemm_mma<32, 0, true, 32><<<gemm_grid, 512, SMEM_BYTES>>>(agg2, nullptr, W2, root2, b2, Y, out, N);
    edge_kernel<<<edge_grid, 256>>>(ei, pseudo, Y, out, E, N);

    relu_kernel<<<(N * 32 + 255) / 256, 256>>>(out, N * 32);
}

// round 7
// speedup vs baseline: 1.8773x; 1.1315x over previous
#include <cuda_runtime.h>
#include <cuda_bf16.h>
#include <cstdint>

// ---------------------------------------------------------------------------
// MeshUpConv: 3x SplineConv (kernel 3x3, degree 2, open spline) on GB300.
//
// R6 -> R7:
//   * GEMM: warp tile 16x80 -> 32x80 (B fragments reused across 2 m-tiles,
//     LDS/MMA 1.6 -> 0.93) and smem stride 34 -> 36 words (bank = (4q+r)%32,
//     a perfect permutation -> zero conflicts on fragment loads).
//   * Edge pass: counting-sort edges by src once per launch (hist + scan +
//     scatter), reused by all 3 edge passes -> Y gathers get L1 locality,
//     L2 traffic drops from ~512MB to ~115MB per pass.
// ---------------------------------------------------------------------------

#define NMAX  50000
#define EMAX  400000
#define CKOUT 288          // K * C_OUT = 9 * 32
#define NCOLS 320          // 288 Y cols + 32 self cols

__device__ float g_Y[(size_t)NMAX * CKOUT];
__device__ float g_agg1[(size_t)NMAX * 32];
__device__ float g_agg2[(size_t)NMAX * 32];

// sort scratch
__device__ int    g_hist[NMAX];
__device__ int    g_off[NMAX];
__device__ int    g_bsum[128];
__device__ int2   g_se[EMAX];     // sorted (src, dst)
__device__ float2 g_sp[EMAX];     // sorted pseudo

// ---- helpers --------------------------------------------------------------
__device__ __forceinline__ uint32_t pack_bf16(float a, float b) {
    __nv_bfloat162 t = __floats2bfloat162_rn(a, b);
    return *reinterpret_cast<uint32_t*>(&t);
}
__device__ __forceinline__ void split_hl(float v, float& h, float& l) {
    __nv_bfloat16 bh = __float2bfloat16_rn(v);
    h = __bfloat162float(bh);
    l = v - h;
}
__device__ __forceinline__ void mma_bf16(float* c,
                                         uint32_t a0, uint32_t a1, uint32_t a2, uint32_t a3,
                                         uint32_t b0, uint32_t b1) {
    asm("mma.sync.aligned.m16n8k16.row.col.f32.bf16.bf16.f32 "
        "{%0,%1,%2,%3}, {%4,%5,%6,%7}, {%8,%9}, {%0,%1,%2,%3};"
        : "+f"(c[0]), "+f"(c[1]), "+f"(c[2]), "+f"(c[3])
        : "r"(a0), "r"(a1), "r"(a2), "r"(a3), "r"(b0), "r"(b1));
}

// SMEM layout. Rows padded to 36 words: bank=(4q+r)%32 -> conflict-free frags.
// A: 128 rows x 32 kpairs; B: 320 rows x 32 kpairs; each hi & lo.
#define ASTR 36
#define SM_BIAS 0
#define SM_A_HI 128
#define SM_A_LO (SM_A_HI + 128 * ASTR * 4)       // 18560
#define SM_B_HI (SM_A_LO + 128 * ASTR * 4)       // 36992
#define SM_B_LO (SM_B_HI + 320 * ASTR * 4)       // 83072
#define SMEM_BYTES (SM_B_LO + 320 * ASTR * 4)    // 129152

// ---------------------------------------------------------------------------
// mma.sync GEMM: per 128-node tile, D[128, 320] = A[128,64] @ Bw[64,320].
// 16 warps = 4(M) x 4(N); warp = 32 rows (2 m-tiles) x 80 cols (10 n-tiles).
// bf16x3 split precision, fp32 accum.
// ---------------------------------------------------------------------------
template<int CA, int CB, bool RELU_A, int CIN_W>
__global__ __launch_bounds__(512)
void gemm_mma(const float* __restrict__ xa, const float* __restrict__ xb,
              const float* __restrict__ W, const float* __restrict__ root,
              const float* __restrict__ bias,
              float* __restrict__ Y, float* __restrict__ agg, int n_nodes)
{
    extern __shared__ __align__(16) char smem[];
    uint32_t* Ah = reinterpret_cast<uint32_t*>(smem + SM_A_HI);
    uint32_t* Al = reinterpret_cast<uint32_t*>(smem + SM_A_LO);
    uint32_t* Bh = reinterpret_cast<uint32_t*>(smem + SM_B_HI);
    uint32_t* Bl = reinterpret_cast<uint32_t*>(smem + SM_B_LO);
    float*    bs = reinterpret_cast<float*>(smem + SM_BIAS);

    const int tid    = threadIdx.x;
    const int wid    = tid >> 5;
    const int lane   = tid & 31;
    const int warp_m = wid >> 2;        // 0..3 -> rows [32*warp_m, +32)
    const int warp_n = wid & 3;         // 0..3 -> cols [80*warp_n, +80)
    constexpr int KSTEPS = CIN_W / 16;

    // ---- Stage B once per CTA: row r = output col, 32 k-pairs (k pad to 64).
    for (int idx = tid; idx < NCOLS * 32; idx += 512) {
        const int r  = idx >> 5;
        const int kp = idx & 31;
        const int i0 = 2 * kp, i1 = i0 + 1;
        float v0 = 0.0f, v1 = 0.0f;
        if (i0 < CIN_W) {
            if (r < CKOUT) {
                const int kk = r >> 5, cc = r & 31;
                v0 = W[(kk * CIN_W + i0) * 32 + cc];
                v1 = W[(kk * CIN_W + i1) * 32 + cc];
            } else {
                v0 = root[i0 * 32 + (r - CKOUT)];
                v1 = root[i1 * 32 + (r - CKOUT)];
            }
        }
        float h0, l0, h1, l1;
        split_hl(v0, h0, l0); split_hl(v1, h1, l1);
        Bh[r * ASTR + kp] = pack_bf16(h0, h1);
        Bl[r * ASTR + kp] = pack_bf16(l0, l1);
    }
    if (tid < 32) bs[tid] = bias[tid];
    __syncthreads();

    const int ntiles = (n_nodes + 127) >> 7;

    for (int t = blockIdx.x; t < ntiles; t += gridDim.x) {
        const int n0 = t << 7;

        // ---- Stage A tile: 128 rows x 32 k-pairs, hi/lo, relu/concat fused.
        for (int idx = tid; idx < 128 * 32; idx += 512) {
            const int row = idx >> 5;
            const int kp  = idx & 31;
            const int n   = n0 + row;
            const int i0  = 2 * kp, i1 = i0 + 1;
            float v0 = 0.0f, v1 = 0.0f;
            if (n < n_nodes) {
                if (i0 < CA) {
                    v0 = xa[(size_t)n * CA + i0];
                    v1 = xa[(size_t)n * CA + i1];
                    if (RELU_A) { v0 = fmaxf(v0, 0.0f); v1 = fmaxf(v1, 0.0f); }
                } else if (CB > 0 && i0 < CA + CB) {
                    v0 = xb[(size_t)n * CB + (i0 - CA)];
                    v1 = xb[(size_t)n * CB + (i1 - CA)];
                }
            }
            float h0, l0, h1, l1;
            split_hl(v0, h0, l0); split_hl(v1, h1, l1);
            Ah[row * ASTR + kp] = pack_bf16(h0, h1);
            Al[row * ASTR + kp] = pack_bf16(l0, l1);
        }
        __syncthreads();

        // ---- Compute: acc[2 m-tiles][10 n-tiles][4]
        float acc[2][10][4];
        #pragma unroll
        for (int mt = 0; mt < 2; mt++)
            #pragma unroll
            for (int nt = 0; nt < 10; nt++)
                #pragma unroll
                for (int j = 0; j < 4; j++) acc[mt][nt][j] = 0.0f;

        const int q   = lane >> 2;
        const int lkp = lane & 3;

        #pragma unroll
        for (int ks = 0; ks < KSTEPS; ks++) {
            const int kpb = ks * 8 + lkp;
            uint32_t ah[2][4], al[2][4];
            #pragma unroll
            for (int mt = 0; mt < 2; mt++) {
                const int g = warp_m * 32 + mt * 16 + q;
                ah[mt][0] = Ah[g * ASTR + kpb];
                ah[mt][1] = Ah[(g + 8) * ASTR + kpb];
                ah[mt][2] = Ah[g * ASTR + kpb + 4];
                ah[mt][3] = Ah[(g + 8) * ASTR + kpb + 4];
                al[mt][0] = Al[g * ASTR + kpb];
                al[mt][1] = Al[(g + 8) * ASTR + kpb];
                al[mt][2] = Al[g * ASTR + kpb + 4];
                al[mt][3] = Al[(g + 8) * ASTR + kpb + 4];
            }
            #pragma unroll
            for (int nt = 0; nt < 10; nt++) {
                const int nrow = warp_n * 80 + nt * 8 + q;
                const uint32_t bh0 = Bh[nrow * ASTR + kpb];
                const uint32_t bh1 = Bh[nrow * ASTR + kpb + 4];
                const uint32_t bl0 = Bl[nrow * ASTR + kpb];
                const uint32_t bl1 = Bl[nrow * ASTR + kpb + 4];
                #pragma unroll
                for (int mt = 0; mt < 2; mt++) {
                    mma_bf16(acc[mt][nt], ah[mt][0], ah[mt][1], ah[mt][2], ah[mt][3], bh0, bh1);
                    mma_bf16(acc[mt][nt], ah[mt][0], ah[mt][1], ah[mt][2], ah[mt][3], bl0, bl1);
                    mma_bf16(acc[mt][nt], al[mt][0], al[mt][1], al[mt][2], al[mt][3], bh0, bh1);
                }
            }
        }

        // ---- Epilogue: d0,d1 -> (row g, col0,col0+1); d2,d3 -> row g+8.
        #pragma unroll
        for (int mt = 0; mt < 2; mt++) {
            const int r0 = n0 + warp_m * 32 + mt * 16 + q;
            const int r1 = r0 + 8;
            #pragma unroll
            for (int nt = 0; nt < 10; nt++) {
                const int col0 = warp_n * 80 + nt * 8 + 2 * lkp;
                if (col0 < CKOUT) {
                    if (r0 < n_nodes)
                        *reinterpret_cast<float2*>(Y + (size_t)r0 * CKOUT + col0)
                            = make_float2(acc[mt][nt][0], acc[mt][nt][1]);
                    if (r1 < n_nodes)
                        *reinterpret_cast<float2*>(Y + (size_t)r1 * CKOUT + col0)
                            = make_float2(acc[mt][nt][2], acc[mt][nt][3]);
                } else {
                    const int a = col0 - CKOUT;
                    const float b0v = bs[a], b1v = bs[a + 1];
                    if (r0 < n_nodes)
                        *reinterpret_cast<float2*>(agg + (size_t)r0 * 32 + a)
                            = make_float2(acc[mt][nt][0] + b0v, acc[mt][nt][1] + b1v);
                    if (r1 < n_nodes)
                        *reinterpret_cast<float2*>(agg + (size_t)r1 * 32 + a)
                            = make_float2(acc[mt][nt][2] + b0v, acc[mt][nt][3] + b1v);
                }
            }
        }
        __syncthreads();
    }
}

// ---------------------------------------------------------------------------
// Counting sort of edges by src (once per launch, reused by 3 edge passes).
// ---------------------------------------------------------------------------
__global__ void hist_zero(int n) {
    const int i = blockIdx.x * blockDim.x + threadIdx.x;
    if (i < n) g_hist[i] = 0;
}
__global__ void hist_kernel(const int* __restrict__ ei, int n_edges) {
    const int e = blockIdx.x * blockDim.x + threadIdx.x;
    if (e < n_edges) atomicAdd(&g_hist[ei[e]], 1);
}
// Block-level exclusive scan (512 bins/block); block totals to g_bsum.
__global__ void scan1(int n) {
    __shared__ int s[512];
    const int tid = threadIdx.x;
    const int b   = blockIdx.x * 512 + tid;
    const int v   = (b < n) ? g_hist[b] : 0;
    s[tid] = v;
    __syncthreads();
    #pragma unroll
    for (int off = 1; off < 512; off <<= 1) {
        int t = (tid >= off) ? s[tid - off] : 0;
        __syncthreads();
        s[tid] += t;
        __syncthreads();
    }
    if (b < n) g_off[b] = s[tid] - v;        // exclusive, block-local
    if (tid == 511) g_bsum[blockIdx.x] = s[511];
}
__global__ void scan2(int nb) {
    if (threadIdx.x == 0 && blockIdx.x == 0) {
        int run = 0;
        for (int i = 0; i < nb; i++) { int t = g_bsum[i]; g_bsum[i] = run; run += t; }
    }
}
__global__ void scan3(int n) {
    const int b = blockIdx.x * 512 + threadIdx.x;
    if (b < n) g_off[b] += g_bsum[blockIdx.x];
}
__global__ void scatter_kernel(const int* __restrict__ ei,
                               const float* __restrict__ pseudo, int n_edges) {
    const int e = blockIdx.x * blockDim.x + threadIdx.x;
    if (e >= n_edges) return;
    const int src = ei[e];
    const int dst = ei[n_edges + e];
    const int pos = atomicAdd(&g_off[src], 1);
    g_se[pos] = make_int2(src, dst);
    g_sp[pos] = reinterpret_cast<const float2*>(pseudo)[e];
}

// ---------------------------------------------------------------------------
// Edge kernel (sorted): 8 lanes per edge, 4 channels per lane (float4).
// Sorted-by-src order -> Y row gathers hit L1/L2 with high locality.
// ---------------------------------------------------------------------------
__global__ __launch_bounds__(256)
void edge_kernel(const float* __restrict__ Y, float* __restrict__ agg,
                 int n_edges, int n_nodes)
{
    const int t   = blockIdx.x * 256 + threadIdx.x;
    const int e   = t >> 3;
    const int sub = t & 7;
    if (e >= n_edges) return;

    const int2   sd = g_se[e];
    const float2 p  = g_sp[e];
    if ((unsigned)sd.x >= (unsigned)n_nodes || (unsigned)sd.y >= (unsigned)n_nodes) return;

    const float q00 = 0.5f * (1.0f - p.x) * (1.0f - p.x);
    const float q01 = -p.x * p.x + p.x + 0.5f;
    const float q02 = 0.5f * p.x * p.x;
    const float q10 = 0.5f * (1.0f - p.y) * (1.0f - p.y);
    const float q11 = -p.y * p.y + p.y + 0.5f;
    const float q12 = 0.5f * p.y * p.y;

    const float b0 = q10 * q00, b1 = q10 * q01, b2 = q10 * q02;
    const float b3 = q11 * q00, b4 = q11 * q01, b5 = q11 * q02;
    const float b6 = q12 * q00, b7 = q12 * q01, b8 = q12 * q02;

    const float4* y = reinterpret_cast<const float4*>(Y + (size_t)sd.x * CKOUT + sub * 4);
    const float4 y0 = y[0*8], y1 = y[1*8], y2 = y[2*8];
    const float4 y3 = y[3*8], y4 = y[4*8], y5 = y[5*8];
    const float4 y6 = y[6*8], y7 = y[7*8], y8 = y[8*8];

    float4 a;
    a.x = b0*y0.x + b1*y1.x + b2*y2.x + b3*y3.x + b4*y4.x + b5*y5.x + b6*y6.x + b7*y7.x + b8*y8.x;
    a.y = b0*y0.y + b1*y1.y + b2*y2.y + b3*y3.y + b4*y4.y + b5*y5.y + b6*y6.y + b7*y7.y + b8*y8.y;
    a.z = b0*y0.z + b1*y1.z + b2*y2.z + b3*y3.z + b4*y4.z + b5*y5.z + b6*y6.z + b7*y7.z + b8*y8.z;
    a.w = b0*y0.w + b1*y1.w + b2*y2.w + b3*y3.w + b4*y4.w + b5*y5.w + b6*y6.w + b7*y7.w + b8*y8.w;

    float* dp = agg + (size_t)sd.y * 32 + sub * 4;
    asm volatile("red.global.add.v4.f32 [%0], {%1, %2, %3, %4};"
                 :: "l"(dp), "f"(a.x), "f"(a.y), "f"(a.z), "f"(a.w) : "memory");
}

__global__ void relu_kernel(float* __restrict__ d, int n)
{
    const int i = blockIdx.x * blockDim.x + threadIdx.x;
    if (i < n) d[i] = fmaxf(d[i], 0.0f);
}

// ---------------------------------------------------------------------------
extern "C" void kernel_launch(void* const* d_in, const int* in_sizes, int n_in,
                              void* d_out, int out_size)
{
    const float* x      = (const float*)d_in[0];
    const int*   ei     = (const int*)d_in[1];     // int64 in ref -> int32 in harness
    const float* pseudo = (const float*)d_in[2];
    const float* skip   = (const float*)d_in[3];
    const float* W1     = (const float*)d_in[4];
    const float* root1  = (const float*)d_in[5];
    const float* b1     = (const float*)d_in[6];
    const float* W2     = (const float*)d_in[7];
    const float* root2  = (const float*)d_in[8];
    const float* b2     = (const float*)d_in[9];

    const int N = in_sizes[0] / 64;
    const int E = in_sizes[1] / 2;
    float* out = (float*)d_out;

    float *Y, *agg1, *agg2;
    cudaGetSymbolAddress((void**)&Y,    g_Y);
    cudaGetSymbolAddress((void**)&agg1, g_agg1);
    cudaGetSymbolAddress((void**)&agg2, g_agg2);

    cudaFuncSetAttribute(gemm_mma<64, 0,  false, 64>,
                         cudaFuncAttributeMaxDynamicSharedMemorySize, SMEM_BYTES);
    cudaFuncSetAttribute(gemm_mma<32, 32, true,  64>,
                         cudaFuncAttributeMaxDynamicSharedMemorySize, SMEM_BYTES);
    cudaFuncSetAttribute(gemm_mma<32, 0,  true,  32>,
                         cudaFuncAttributeMaxDynamicSharedMemorySize, SMEM_BYTES);

    const int gemm_grid = 148;
    const int edge_grid = (E * 8 + 255) / 256;
    const int NB        = (N + 511) / 512;

    // ---- Sort edges by src (once; reused by all 3 edge passes).
    hist_zero<<<NB, 512>>>(N);
    hist_kernel<<<(E + 255) / 256, 256>>>(ei, E);
    scan1<<<NB, 512>>>(N);
    scan2<<<1, 32>>>(NB);
    scan3<<<NB, 512>>>(N);
    scatter_kernel<<<(E + 255) / 256, 256>>>(ei, pseudo, E);

    // Layer 1: x[N,64] -> agg1
    gemm_mma<64, 0, false, 64><<<gemm_grid, 512, SMEM_BYTES>>>(x, nullptr, W1, root1, b1, Y, agg1, N);
    edge_kernel<<<edge_grid, 256>>>(Y, agg1, E, N);

    // Layer 2: concat(relu(agg1), skip)[N,64] -> agg2   (same W1/root1/b1)
    gemm_mma<32, 32, true, 64><<<gemm_grid, 512, SMEM_BYTES>>>(agg1, skip, W1, root1, b1, Y, agg2, N);
    edge_kernel<<<edge_grid, 256>>>(Y, agg2, E, N);

    // Layer 3: relu(agg2)[N,32] -> d_out  (K = 32 -> 2 k-steps)
    gemm_mma<32, 0, true, 32><<<gemm_grid, 512, SMEM_BYTES>>>(agg2, nullptr, W2, root2, b2, Y, out, N);
    edge_kernel<<<edge_grid, 256>>>(Y, out, E, N);

    relu_kernel<<<(N * 32 + 255) / 256, 256>>>(out, N * 32);
}